// round 1
// baseline (speedup 1.0000x reference)
#include <cuda_runtime.h>
#include <cuda_bf16.h>

// Problem constants (B=2, T=256, E=256, H=4)
#define E_DIM 256
#define H_DIM 4
#define EH_DIM 1024
#define BT_DIM 512   // B*T

// Scratch for the combined weight matrix C[f][e] (f = input feature of values,
// e = output feature). __device__ global: no allocation at runtime.
__device__ float g_C[E_DIM * E_DIM];

// ---------------------------------------------------------------------------
// Kernel 1: C[f,e] = sum_c Wv[c, f] * Wp[e, perm(c)]
//   where c = h*E + d  (Wv output channel index), perm(c) = d*H + h
//   (the reference's chunk/stack + flatten(-2) permutation folded into Wp).
// 256x256 output, K = 1024. 32x32 tile, 1024 threads/block, grid 8x8.
// ---------------------------------------------------------------------------
__global__ __launch_bounds__(1024) void build_C_kernel(
    const float* __restrict__ Wv,   // [EH, E] row-major
    const float* __restrict__ Wp)   // [E, EH] row-major
{
    __shared__ float sWv[32][33];   // [c_local][f_local]
    __shared__ float sWp[32][33];   // [c_local][e_local]

    const int tx = threadIdx.x;     // f_local (compute) / varies for loads
    const int ty = threadIdx.y;     // e_local (compute)
    const int f = blockIdx.x * 32 + tx;
    const int e = blockIdx.y * 32 + ty;

    float acc = 0.0f;

    for (int c0 = 0; c0 < EH_DIM; c0 += 32) {
        // Load Wv tile: coalesced along f (tx).
        sWv[ty][tx] = Wv[(c0 + ty) * E_DIM + blockIdx.x * 32 + tx];

        // Load permuted-Wp tile: tx walks c (gmem stride H*4B = 16B within a
        // row — 4 lines per warp, L2-resident). Store stride 33 -> no bank
        // conflicts.
        int c = c0 + tx;
        int d = c & (E_DIM - 1);
        int h = c >> 8;
        sWp[tx][ty] = Wp[(blockIdx.y * 32 + ty) * EH_DIM + d * H_DIM + h];

        __syncthreads();

        #pragma unroll
        for (int k = 0; k < 32; k++)
            acc += sWv[k][tx] * sWp[k][ty];   // stride-1 + broadcast: conflict-free

        __syncthreads();
    }

    g_C[f * E_DIM + e] = acc;
}

// ---------------------------------------------------------------------------
// Kernel 2: out[m, e] = sum_f values[m, f] * C[f, e],  m in [0, B*T)
// 512x256 output, K = 256. 32x32 tile, grid 8x16.
// ---------------------------------------------------------------------------
__global__ __launch_bounds__(1024) void gemm_out_kernel(
    const float* __restrict__ values,   // [BT, E]
    float* __restrict__ out)            // [BT, E]
{
    __shared__ float sV[32][33];   // [m_local][f_local]
    __shared__ float sC[32][33];   // [f_local][e_local]

    const int tx = threadIdx.x;    // e_local
    const int ty = threadIdx.y;    // m_local
    const int e = blockIdx.x * 32 + tx;
    const int m = blockIdx.y * 32 + ty;

    float acc = 0.0f;

    for (int f0 = 0; f0 < E_DIM; f0 += 32) {
        sV[ty][tx] = values[(blockIdx.y * 32 + ty) * E_DIM + f0 + tx];     // coalesced
        sC[ty][tx] = g_C[(f0 + ty) * E_DIM + blockIdx.x * 32 + tx];        // coalesced
        __syncthreads();

        #pragma unroll
        for (int k = 0; k < 32; k++)
            acc += sV[ty][k] * sC[k][tx];   // broadcast + stride-1: conflict-free

        __syncthreads();
    }

    out[m * E_DIM + e] = acc;
}

// ---------------------------------------------------------------------------
// Input order (metadata): 0=position_embeddings, 1=values, 2=ln_w, 3=ln_b,
//                         4=Wq, 5=Wk, 6=Wv, 7=Wp.  Output: float [B,T,E].
// The softmax over w sums to 1, so out = Vh; LN/Q/K never touch the output.
// ---------------------------------------------------------------------------
extern "C" void kernel_launch(void* const* d_in, const int* in_sizes, int n_in,
                              void* d_out, int out_size)
{
    const float* values = (const float*)d_in[1];
    const float* Wv     = (const float*)d_in[6];
    const float* Wp     = (const float*)d_in[7];
    float* out          = (float*)d_out;

    dim3 threads(32, 32);
    build_C_kernel<<<dim3(8, 8), threads>>>(Wv, Wp);
    gemm_out_kernel<<<dim3(8, 16), threads>>>(values, out);
}

// round 2
// speedup vs baseline: 2.6022x; 2.6022x over previous
#include <cuda_runtime.h>
#include <cuda_bf16.h>

// Problem constants (B=2, T=256, E=256, H=4)
#define E_DIM  256
#define H_DIM  4
#define EH_DIM 1024
#define BT_DIM 512
#define SPLITK 8
#define PCHUNK 128          // EH_DIM / SPLITK

// Split-K partials for C[f][e] (plain stores -> deterministic), then reduced.
__device__ float g_Cp[SPLITK][E_DIM * E_DIM];   // 2 MB
__device__ float g_C[E_DIM * E_DIM];            // 256 KB

// ---------------------------------------------------------------------------
// Kernel 1: partial C.  C[f,e] = sum_p Wv[c(p), f] * Wp[e, p]
//   contraction relabeled by p = d*H + h  (Wp's native column index), so
//   c(p) = h*E + d = (p&3)*256 + (p>>2).  Both operands now load coalesced.
// 64x64 tile, 4x4 register micro-tile, 256 threads, grid (4,4,SPLITK).
// ---------------------------------------------------------------------------
__global__ __launch_bounds__(256) void build_C_kernel(
    const float* __restrict__ Wv,   // [EH, E] row-major
    const float* __restrict__ Wp)   // [E, EH] row-major
{
    __shared__ float sA[16][64];    // [p_local][f_local]  (row = 256B, 16B-aligned)
    __shared__ float sB[16][68];    // [p_local][e_local]  (pad 68 -> 272B, 16B-aligned)

    const int tid = threadIdx.x;
    const int tx  = tid & 15;       // f micro-tile group
    const int ty  = tid >> 4;       // e micro-tile group
    const int f0  = blockIdx.x * 64;
    const int e0  = blockIdx.y * 64;
    const int p0  = blockIdx.z * PCHUNK;

    float acc[4][4];
    #pragma unroll
    for (int i = 0; i < 4; i++)
        #pragma unroll
        for (int j = 0; j < 4; j++) acc[i][j] = 0.0f;

    // load-index precompute
    const int lA_pc = tid >> 4;            // 0..15
    const int lA_f4 = (tid & 15) * 4;
    const int lB_e  = tid >> 2;            // 0..63
    const int lB_p4 = (tid & 3) * 4;

    for (int ps0 = 0; ps0 < PCHUNK; ps0 += 16) {
        // A tile: row c(p), coalesced 256B rows
        {
            int p = p0 + ps0 + lA_pc;
            int c = ((p & 3) << 8) + (p >> 2);
            *(float4*)&sA[lA_pc][lA_f4] =
                *(const float4*)&Wv[c * E_DIM + f0 + lA_f4];
        }
        // B tile: Wp row e, 16 consecutive p -> one 64B sector, 100% efficient
        {
            float4 b4 = *(const float4*)&Wp[(e0 + lB_e) * EH_DIM + p0 + ps0 + lB_p4];
            sB[lB_p4 + 0][lB_e] = b4.x;
            sB[lB_p4 + 1][lB_e] = b4.y;
            sB[lB_p4 + 2][lB_e] = b4.z;
            sB[lB_p4 + 3][lB_e] = b4.w;
        }
        __syncthreads();

        #pragma unroll
        for (int ps = 0; ps < 16; ps++) {
            float4 a = *(float4*)&sA[ps][tx * 4];
            float4 b = *(float4*)&sB[ps][ty * 4];
            acc[0][0] += a.x * b.x; acc[0][1] += a.x * b.y;
            acc[0][2] += a.x * b.z; acc[0][3] += a.x * b.w;
            acc[1][0] += a.y * b.x; acc[1][1] += a.y * b.y;
            acc[1][2] += a.y * b.z; acc[1][3] += a.y * b.w;
            acc[2][0] += a.z * b.x; acc[2][1] += a.z * b.y;
            acc[2][2] += a.z * b.z; acc[2][3] += a.z * b.w;
            acc[3][0] += a.w * b.x; acc[3][1] += a.w * b.y;
            acc[3][2] += a.w * b.z; acc[3][3] += a.w * b.w;
        }
        __syncthreads();
    }

    float* dst = &g_Cp[blockIdx.z][0];
    #pragma unroll
    for (int i = 0; i < 4; i++) {
        int f = f0 + tx * 4 + i;
        *(float4*)&dst[f * E_DIM + e0 + ty * 4] =
            make_float4(acc[i][0], acc[i][1], acc[i][2], acc[i][3]);
    }
}

// ---------------------------------------------------------------------------
// Kernel 2: reduce split-K partials.  g_C = sum_z g_Cp[z]
// ---------------------------------------------------------------------------
__global__ __launch_bounds__(256) void reduce_C_kernel()
{
    int idx4 = (blockIdx.x * 256 + threadIdx.x) * 4;   // 64 blocks cover 65536
    float4 s = *(const float4*)&g_Cp[0][idx4];
    #pragma unroll
    for (int z = 1; z < SPLITK; z++) {
        float4 v = *(const float4*)&g_Cp[z][idx4];
        s.x += v.x; s.y += v.y; s.z += v.z; s.w += v.w;
    }
    *(float4*)&g_C[idx4] = s;
}

// ---------------------------------------------------------------------------
// Kernel 3: out[m,e] = sum_f values[m,f] * C[f,e]
// 32x32 tile, 2x2 micro-tile, 256 threads, grid (8 e-tiles, 16 m-tiles).
// ---------------------------------------------------------------------------
__global__ __launch_bounds__(256) void gemm_out_kernel(
    const float* __restrict__ values,   // [BT, E]
    float* __restrict__ out)            // [BT, E]
{
    __shared__ float sV[32][20];   // [m][f_local], stride 80B (16B-aligned)
    __shared__ float sC[16][36];   // [f_local][e], stride 144B (16B-aligned)

    const int tid = threadIdx.x;
    const int tx  = tid & 15;      // e pair
    const int ty  = tid >> 4;      // m pair
    const int e0  = blockIdx.x * 32;
    const int m0  = blockIdx.y * 32;

    float acc00 = 0.f, acc01 = 0.f, acc10 = 0.f, acc11 = 0.f;

    const int lV_m  = tid >> 3;           // 0..31
    const int lV_f2 = (tid & 7) * 2;
    const int lC_f  = tid >> 4;           // 0..15
    const int lC_e2 = (tid & 15) * 2;

    for (int f0 = 0; f0 < E_DIM; f0 += 16) {
        {
            float2 v = *(const float2*)&values[(m0 + lV_m) * E_DIM + f0 + lV_f2];
            sV[lV_m][lV_f2]     = v.x;
            sV[lV_m][lV_f2 + 1] = v.y;
        }
        {
            float2 c = *(const float2*)&g_C[(f0 + lC_f) * E_DIM + e0 + lC_e2];
            sC[lC_f][lC_e2]     = c.x;
            sC[lC_f][lC_e2 + 1] = c.y;
        }
        __syncthreads();

        #pragma unroll
        for (int ps = 0; ps < 16; ps++) {
            float a0 = sV[ty * 2][ps];
            float a1 = sV[ty * 2 + 1][ps];
            float2 b = *(float2*)&sC[ps][tx * 2];
            acc00 += a0 * b.x; acc01 += a0 * b.y;
            acc10 += a1 * b.x; acc11 += a1 * b.y;
        }
        __syncthreads();
    }

    *(float2*)&out[(m0 + ty * 2) * E_DIM + e0 + tx * 2]     = make_float2(acc00, acc01);
    *(float2*)&out[(m0 + ty * 2 + 1) * E_DIM + e0 + tx * 2] = make_float2(acc10, acc11);
}

// ---------------------------------------------------------------------------
// softmax over w sums to 1 => out = Vh; only values, Wv, Wp matter.
// Inputs: 0=pos_emb, 1=values, 2=ln_w, 3=ln_b, 4=Wq, 5=Wk, 6=Wv, 7=Wp.
// ---------------------------------------------------------------------------
extern "C" void kernel_launch(void* const* d_in, const int* in_sizes, int n_in,
                              void* d_out, int out_size)
{
    const float* values = (const float*)d_in[1];
    const float* Wv     = (const float*)d_in[6];
    const float* Wp     = (const float*)d_in[7];
    float* out          = (float*)d_out;

    build_C_kernel<<<dim3(4, 4, SPLITK), 256>>>(Wv, Wp);
    reduce_C_kernel<<<64, 256>>>();
    gemm_out_kernel<<<dim3(8, 16), 256>>>(values, out);
}

// round 4
// speedup vs baseline: 2.9936x; 1.1504x over previous
#include <cuda_runtime.h>
#include <cuda_bf16.h>

// Problem constants (B=2, T=256, E=256, H=4)
#define E_DIM  256
#define H_DIM  4
#define EH_DIM 1024
#define BT_DIM 512
#define SPLITK 16
#define PCHUNK 64           // EH_DIM / SPLITK

typedef unsigned long long u64;

// Packed fp32x2 helpers (sm_100+): one instruction, two fp32 FMAs.
#define PACK2(d, lo, hi) asm("mov.b64 %0, {%1, %2};" : "=l"(d) : "f"(lo), "f"(hi))
#define FMA2(d, a, b)    asm("fma.rn.f32x2 %0, %1, %2, %0;" : "+l"(d) : "l"(a), "l"(b))
#define UNPACK2(lo, hi, s) asm("mov.b64 {%0, %1}, %2;" : "=f"(lo), "=f"(hi) : "l"(s))

// Split-K partials for C[f][e] (plain stores -> deterministic), then reduced.
__device__ float g_Cp[SPLITK][E_DIM * E_DIM];   // 4 MB
__device__ float g_C[E_DIM * E_DIM];            // 256 KB

// ---------------------------------------------------------------------------
// Kernel 1: partial C.  C[f,e] = sum_p Wv[c(p), f] * Wp[e, p]
//   p = d*H + h (Wp-native), c(p) = (p&3)*256 + (p>>2).  Both loads coalesced.
// 64x64 tile, 4x4 micro-tile (f32x2-packed along f), 256 thr, grid (4,4,16).
// ---------------------------------------------------------------------------
__global__ __launch_bounds__(256) void build_C_kernel(
    const float* __restrict__ Wv,   // [EH, E] row-major
    const float* __restrict__ Wp)   // [E, EH] row-major
{
    __shared__ __align__(16) float sA[16][64];   // [p_local][f_local]
    __shared__ __align__(16) float sB[16][68];   // [p_local][e_local] (pad)

    const int tid = threadIdx.x;
    const int tx  = tid & 15;       // f group
    const int ty  = tid >> 4;       // e group
    const int f0  = blockIdx.x * 64;
    const int e0  = blockIdx.y * 64;
    const int p0  = blockIdx.z * PCHUNK;

    // 8 packed accumulators: acc01[j] = (f_i0, f_i1) for column j; acc23 = (f_i2, f_i3)
    u64 acc01[4], acc23[4];
    #pragma unroll
    for (int j = 0; j < 4; j++) { PACK2(acc01[j], 0.0f, 0.0f); PACK2(acc23[j], 0.0f, 0.0f); }

    const int lA_pc = tid >> 4;            // 0..15
    const int lA_f4 = (tid & 15) * 4;
    const int lB_e  = tid >> 2;            // 0..63
    const int lB_p4 = (tid & 3) * 4;

    // --- prefetch iter 0 ---
    float4 pa, pb;
    {
        int p = p0 + lA_pc;
        int c = ((p & 3) << 8) + (p >> 2);
        pa = *(const float4*)&Wv[c * E_DIM + f0 + lA_f4];
        pb = *(const float4*)&Wp[(e0 + lB_e) * EH_DIM + p0 + lB_p4];
    }

    #pragma unroll
    for (int it = 0; it < PCHUNK / 16; it++) {
        *(float4*)&sA[lA_pc][lA_f4] = pa;
        sB[lB_p4 + 0][lB_e] = pb.x;
        sB[lB_p4 + 1][lB_e] = pb.y;
        sB[lB_p4 + 2][lB_e] = pb.z;
        sB[lB_p4 + 3][lB_e] = pb.w;
        __syncthreads();

        if (it < PCHUNK / 16 - 1) {   // prefetch next tile (hidden under compute)
            int p = p0 + (it + 1) * 16 + lA_pc;
            int c = ((p & 3) << 8) + (p >> 2);
            pa = *(const float4*)&Wv[c * E_DIM + f0 + lA_f4];
            pb = *(const float4*)&Wp[(e0 + lB_e) * EH_DIM + p0 + (it + 1) * 16 + lB_p4];
        }

        #pragma unroll
        for (int ps = 0; ps < 16; ps++) {
            float4 a = *(float4*)&sA[ps][tx * 4];
            float4 b = *(float4*)&sB[ps][ty * 4];
            u64 a01, a23, bd0, bd1, bd2, bd3;
            PACK2(a01, a.x, a.y);
            PACK2(a23, a.z, a.w);
            PACK2(bd0, b.x, b.x); FMA2(acc01[0], a01, bd0); FMA2(acc23[0], a23, bd0);
            PACK2(bd1, b.y, b.y); FMA2(acc01[1], a01, bd1); FMA2(acc23[1], a23, bd1);
            PACK2(bd2, b.z, b.z); FMA2(acc01[2], a01, bd2); FMA2(acc23[2], a23, bd2);
            PACK2(bd3, b.w, b.w); FMA2(acc01[3], a01, bd3); FMA2(acc23[3], a23, bd3);
        }
        __syncthreads();
    }

    // epilogue: unpack 16 results, store 4 x STG.128
    float r[4][4];
    #pragma unroll
    for (int j = 0; j < 4; j++) {
        UNPACK2(r[0][j], r[1][j], acc01[j]);
        UNPACK2(r[2][j], r[3][j], acc23[j]);
    }
    float* dst = &g_Cp[blockIdx.z][0];
    #pragma unroll
    for (int i = 0; i < 4; i++) {
        int f = f0 + tx * 4 + i;
        *(float4*)&dst[f * E_DIM + e0 + ty * 4] =
            make_float4(r[i][0], r[i][1], r[i][2], r[i][3]);
    }
}

// ---------------------------------------------------------------------------
// Kernel 2: g_C = sum_z g_Cp[z]   (fixed z order -> deterministic)
// ---------------------------------------------------------------------------
__global__ __launch_bounds__(256) void reduce_C_kernel()
{
    int idx4 = (blockIdx.x * 256 + threadIdx.x) * 4;   // 64 blocks cover 65536
    float4 s = *(const float4*)&g_Cp[0][idx4];
    #pragma unroll
    for (int z = 1; z < SPLITK; z++) {
        float4 v = *(const float4*)&g_Cp[z][idx4];
        s.x += v.x; s.y += v.y; s.z += v.z; s.w += v.w;
    }
    *(float4*)&g_C[idx4] = s;
}

// ---------------------------------------------------------------------------
// Kernel 3: out[m,e] = sum_f values[m,f] * C[f,e]
// 32x32 tile, 2x2 micro (f32x2 along m), 256 thr, grid (8,16) = 128 CTAs.
// sV transposed to [f][m] so both operands read as float2.
// ---------------------------------------------------------------------------
__global__ __launch_bounds__(256) void gemm_out_kernel(
    const float* __restrict__ values,   // [BT, E]
    float* __restrict__ out)            // [BT, E]
{
    __shared__ __align__(8) float sV[16][34];   // [f_local][m], pad->8B-aligned rows
    __shared__ __align__(8) float sC[16][34];   // [f_local][e]

    const int tid = threadIdx.x;
    const int tx  = tid & 15;      // e pair
    const int ty  = tid >> 4;      // m pair
    const int e0  = blockIdx.x * 32;
    const int m0  = blockIdx.y * 32;

    u64 accj0, accj1;              // (m0,m1) packed, for e=2tx and e=2tx+1
    PACK2(accj0, 0.0f, 0.0f);
    PACK2(accj1, 0.0f, 0.0f);

    const int lV_m  = tid >> 3;           // 0..31
    const int lV_f2 = (tid & 7) * 2;      // 0..14
    const int lC_f  = tid >> 4;           // 0..15
    const int lC_e2 = (tid & 15) * 2;     // 0..30

    float2 pv = *(const float2*)&values[(m0 + lV_m) * E_DIM + lV_f2];
    float2 pc = *(const float2*)&g_C[lC_f * E_DIM + e0 + lC_e2];

    #pragma unroll
    for (int it = 0; it < E_DIM / 16; it++) {
        sV[lV_f2][lV_m]     = pv.x;       // transposed store
        sV[lV_f2 + 1][lV_m] = pv.y;
        *(float2*)&sC[lC_f][lC_e2] = pc;
        __syncthreads();

        if (it < E_DIM / 16 - 1) {
            int f0 = (it + 1) * 16;
            pv = *(const float2*)&values[(m0 + lV_m) * E_DIM + f0 + lV_f2];
            pc = *(const float2*)&g_C[(f0 + lC_f) * E_DIM + e0 + lC_e2];
        }

        #pragma unroll
        for (int ps = 0; ps < 16; ps++) {
            float2 a = *(float2*)&sV[ps][ty * 2];   // (m0, m1)
            float2 b = *(float2*)&sC[ps][tx * 2];   // (e0, e1)
            u64 a01, bd0, bd1;
            PACK2(a01, a.x, a.y);
            PACK2(bd0, b.x, b.x); FMA2(accj0, a01, bd0);
            PACK2(bd1, b.y, b.y); FMA2(accj1, a01, bd1);
        }
        __syncthreads();
    }

    float o00, o10, o01, o11;
    UNPACK2(o00, o10, accj0);
    UNPACK2(o01, o11, accj1);
    *(float2*)&out[(m0 + ty * 2) * E_DIM + e0 + tx * 2]     = make_float2(o00, o01);
    *(float2*)&out[(m0 + ty * 2 + 1) * E_DIM + e0 + tx * 2] = make_float2(o10, o11);
}

// ---------------------------------------------------------------------------
// softmax over w sums to 1 => out = Vh; only values, Wv, Wp matter.
// Inputs: 0=pos_emb, 1=values, 2=ln_w, 3=ln_b, 4=Wq, 5=Wk, 6=Wv, 7=Wp.
// ---------------------------------------------------------------------------
extern "C" void kernel_launch(void* const* d_in, const int* in_sizes, int n_in,
                              void* d_out, int out_size)
{
    const float* values = (const float*)d_in[1];
    const float* Wv     = (const float*)d_in[6];
    const float* Wp     = (const float*)d_in[7];
    float* out          = (float*)d_out;

    build_C_kernel<<<dim3(4, 4, SPLITK), 256>>>(Wv, Wp);
    reduce_C_kernel<<<64, 256>>>();
    gemm_out_kernel<<<dim3(8, 16), 256>>>(values, out);
}